// round 9
// baseline (speedup 1.0000x reference)
#include <cuda_runtime.h>
#include <cuda_bf16.h>
#include <math.h>
#include <stdint.h>

static constexpr int F    = 128;
static constexpr int NMAX = 50000;
static constexpr int NPAD = 50048;     // rounded up to 128-row tiles; padding rows stay zero
static constexpr int EMAX = 800000;

// ---- tc_gemm smem layout (bytes) ----
static constexpr int SM_BH   = 0;        // 128 rows x 528 B  (264 bf16: 256 + 8 pad)
static constexpr int SM_BL   = 67584;
static constexpr int SM_A    = 135168;   // 4 bufs x 18432 B (128 rows x 144 B = 72 bf16: 64 + 8 pad)
static constexpr int ABUF_SZ = 18432;
static constexpr int TC_SMEM = SM_A + 4 * ABUF_SZ;   // 208896
static constexpr int BSTR = 264;
static constexpr int ASTRB = 72;

// ---------------- scratch ----------------
__device__ __align__(256) float g_xagg[NMAX * F];
__device__ __align__(256) float g_Z   [NMAX * F];
__device__ __align__(256) float g_cb  [3 * F];
__device__ __align__(256) __nv_bfloat16 g_Bh[3 * F * 256];
__device__ __align__(256) __nv_bfloat16 g_Bl[3 * F * 256];
__device__ __align__(256) __nv_bfloat16 g_Xh [NPAD * F];
__device__ __align__(256) __nv_bfloat16 g_Xl [NPAD * F];
__device__ __align__(256) __nv_bfloat16 g_Hh [NPAD * F];
__device__ __align__(256) __nv_bfloat16 g_Hl [NPAD * F];
__device__ __align__(256) __nv_bfloat16 g_HRh[NPAD * F];
__device__ __align__(256) __nv_bfloat16 g_HRl[NPAD * F];
__device__ float g_deg [NMAX];
__device__ float g_dinv[NMAX];
__device__ int   g_src [EMAX];
__device__ int   g_tgt [EMAX];
__device__ int   g_is64;

// ---------------- helpers ----------------
__device__ __forceinline__ uint32_t smem_u32(const void* p) {
    uint32_t a;
    asm("{ .reg .u64 t; cvta.to.shared.u64 t, %1; cvt.u32.u64 %0, t; }" : "=r"(a) : "l"(p));
    return a;
}
__device__ __forceinline__ void ldm_x4(uint32_t* r, uint32_t addr) {
    asm volatile("ldmatrix.sync.aligned.m8n8.x4.shared.b16 {%0,%1,%2,%3}, [%4];"
                 : "=r"(r[0]), "=r"(r[1]), "=r"(r[2]), "=r"(r[3]) : "r"(addr));
}
__device__ __forceinline__ void mma_bf16(float* c, const uint32_t* a, uint32_t b0, uint32_t b1) {
    asm volatile("mma.sync.aligned.m16n8k16.row.col.f32.bf16.bf16.f32 "
                 "{%0,%1,%2,%3}, {%4,%5,%6,%7}, {%8,%9}, {%0,%1,%2,%3};"
                 : "+f"(c[0]), "+f"(c[1]), "+f"(c[2]), "+f"(c[3])
                 : "r"(a[0]), "r"(a[1]), "r"(a[2]), "r"(a[3]), "r"(b0), "r"(b1));
}
__device__ __forceinline__ uint32_t pack_bf2(float a, float b) {
    __nv_bfloat16 ha = __float2bfloat16(a), hb = __float2bfloat16(b);
    return ((uint32_t)__bfloat16_as_ushort(hb) << 16) | (uint32_t)__bfloat16_as_ushort(ha);
}
#define CP_ASYNC16(dst, src) \
    asm volatile("cp.async.cg.shared.global [%0], [%1], 16;" :: "r"(dst), "l"(src))
#define CP_COMMIT() asm volatile("cp.async.commit_group;" ::: "memory")
#define CP_WAIT0()  asm volatile("cp.async.wait_group 0;" ::: "memory")
#define CP_WAIT1()  asm volatile("cp.async.wait_group 1;" ::: "memory")

// ---------------- epilogue functors ----------------
struct EpiZ {
    float* Zp;
    __device__ __forceinline__ void operator()(size_t o, float v0, float v1) const {
        float2 r;
        r.x = 1.f / (1.f + __expf(-v0));
        r.y = 1.f / (1.f + __expf(-v1));
        *(float2*)(Zp + o) = r;
    }
};
struct EpiHR {   // writes HR directly as split bf16 (same values as in-GEMM split)
    __nv_bfloat16* HRh;
    __nv_bfloat16* HRl;
    const float* H;
    __device__ __forceinline__ void operator()(size_t o, float v0, float v1) const {
        float hr0 = H[o]     * (1.f / (1.f + __expf(-v0)));
        float hr1 = H[o + 1] * (1.f / (1.f + __expf(-v1)));
        __nv_bfloat16 h0 = __float2bfloat16(hr0), h1 = __float2bfloat16(hr1);
        uint32_t hi = ((uint32_t)__bfloat16_as_ushort(h1) << 16) | __bfloat16_as_ushort(h0);
        uint32_t lo = pack_bf2(hr0 - __bfloat162float(h0), hr1 - __bfloat162float(h1));
        *(uint32_t*)(HRh + o) = hi;
        *(uint32_t*)(HRl + o) = lo;
    }
};
struct EpiFinal {
    float* out;
    const float* Zb;
    const float* H;
    __device__ __forceinline__ void operator()(size_t o, float v0, float v1) const {
        float z0 = Zb[o], z1 = Zb[o + 1];
        float2 r;
        r.x = z0 * H[o]     + (1.f - z0) * tanhf(v0);
        r.y = z1 * H[o + 1] + (1.f - z1) * tanhf(v1);
        *(float2*)(out + o) = r;
    }
};

// ---------------- prep kernels ----------------
__global__ void probe_kernel(const int* __restrict__ w) {
    __shared__ int nz;
    if (threadIdx.x == 0) nz = 0;
    __syncthreads();
    int local = 0;
    for (int i = threadIdx.x; i < 1024; i += blockDim.x)
        if (w[2 * i + 1] != 0) local = 1;
    if (local) atomicOr(&nz, 1);
    __syncthreads();
    if (threadIdx.x == 0) g_is64 = (nz == 0) ? 1 : 0;
}

__global__ void decode_deg_kernel(const int* __restrict__ w,
                                  const float* __restrict__ ew, int E) {
    int e = blockIdx.x * blockDim.x + threadIdx.x;
    if (e >= E) return;
    int s, t;
    if (g_is64) { s = w[2 * e]; t = w[2 * (E + e)]; }
    else        { s = w[e];     t = w[E + e];       }
    g_src[e] = s;
    g_tgt[e] = t;
    atomicAdd(&g_deg[t], ew[e]);
}

__global__ void initdeg_kernel(int n) {
    int i = blockIdx.x * blockDim.x + threadIdx.x;
    if (i < n) g_deg[i] = 1.0f;
}
__global__ void dinv_kernel(int n) {
    int i = blockIdx.x * blockDim.x + threadIdx.x;
    if (i < n) g_dinv[i] = rsqrtf(g_deg[i]);
}
__global__ void xinit_kernel(const float* __restrict__ X, int n) {
    int i4 = blockIdx.x * blockDim.x + threadIdx.x;
    if (i4 >= n * (F / 4)) return;
    int node = i4 >> 5;
    float d = g_dinv[node];
    float d2 = d * d;
    float4 v = ((const float4*)X)[i4];
    ((float4*)g_xagg)[i4] = make_float4(v.x * d2, v.y * d2, v.z * d2, v.w * d2);
}

__global__ void scatter_kernel(const float* __restrict__ X,
                               const float* __restrict__ ew, int E) {
    int gw   = (blockIdx.x * blockDim.x + threadIdx.x) >> 5;
    int lane = threadIdx.x & 31;
    if (gw >= E) return;
    int s = g_src[gw];
    int t = g_tgt[gw];
    float c = g_dinv[s] * ew[gw] * g_dinv[t];
    const float4* xp = (const float4*)(X + (size_t)s * F);
    float*        ap = g_xagg + (size_t)t * F + lane * 4;
    float4 v = __ldg(xp + lane);
    asm volatile("red.global.add.v4.f32 [%0], {%1, %2, %3, %4};"
                 :: "l"(ap), "f"(v.x * c), "f"(v.y * c), "f"(v.z * c), "f"(v.w * c)
                 : "memory");
}

// generic fp32 -> split-bf16 conversion (4 elems per thread)
__global__ void split_kernel(const float* __restrict__ src,
                             __nv_bfloat16* __restrict__ dh,
                             __nv_bfloat16* __restrict__ dl, int n4) {
    int i4 = blockIdx.x * blockDim.x + threadIdx.x;
    if (i4 >= n4) return;
    float4 v = ((const float4*)src)[i4];
    __nv_bfloat16 h0 = __float2bfloat16(v.x), h1 = __float2bfloat16(v.y);
    __nv_bfloat16 h2 = __float2bfloat16(v.z), h3 = __float2bfloat16(v.w);
    uint2 hi, lo;
    hi.x = ((uint32_t)__bfloat16_as_ushort(h1) << 16) | __bfloat16_as_ushort(h0);
    hi.y = ((uint32_t)__bfloat16_as_ushort(h3) << 16) | __bfloat16_as_ushort(h2);
    lo.x = pack_bf2(v.x - __bfloat162float(h0), v.y - __bfloat162float(h1));
    lo.y = pack_bf2(v.z - __bfloat162float(h2), v.w - __bfloat162float(h3));
    ((uint2*)dh)[i4] = hi;
    ((uint2*)dl)[i4] = lo;
}

__global__ void biasprep_kernel(const float* __restrict__ bz, const float* __restrict__ Wlz, const float* __restrict__ blz,
                                const float* __restrict__ br, const float* __restrict__ Wlr, const float* __restrict__ blr,
                                const float* __restrict__ bh, const float* __restrict__ Wlh, const float* __restrict__ blh) {
    int t = threadIdx.x;               // 384 threads
    int ch = t >> 7, j = t & 127;
    const float* b  = (ch == 0) ? bz  : (ch == 1) ? br  : bh;
    const float* Wl = (ch == 0) ? Wlz : (ch == 1) ? Wlr : Wlh;
    const float* bl = (ch == 0) ? blz : (ch == 1) ? blr : blh;
    float acc = bl[j];
    for (int k = 0; k < F; k++) acc += b[k] * Wl[k * F + j];
    g_cb[ch * F + j] = acc;
}

// B images [ch][n][k]: k<128 -> (W_ch @ Wl_ch_top)[k][n]; k>=128 -> Wl[k][n].
__global__ void bprep_kernel(const float* __restrict__ Wz, const float* __restrict__ Wr, const float* __restrict__ Wh,
                             const float* __restrict__ Wlz, const float* __restrict__ Wlr, const float* __restrict__ Wlh) {
    __shared__ float wrow[128];
    int bid = blockIdx.x;
    int ch = bid >> 8, k = bid & 255;
    int n = threadIdx.x;
    const float* Wl = (ch == 0) ? Wlz : (ch == 1) ? Wlr : Wlh;
    float v;
    if (k < 128) {
        const float* W = (ch == 0) ? Wz : (ch == 1) ? Wr : Wh;
        wrow[n] = W[k * F + n];
        __syncthreads();
        float acc = 0.f;
#pragma unroll 8
        for (int j = 0; j < F; j++) acc += wrow[j] * Wl[j * F + n];
        v = acc;
    } else {
        v = Wl[k * F + n];
    }
    __nv_bfloat16 h = __float2bfloat16(v);
    __nv_bfloat16 l = __float2bfloat16(v - __bfloat162float(h));
    size_t o = (size_t)ch * F * 256 + (size_t)n * 256 + k;
    g_Bh[o] = h;
    g_Bl[o] = l;
}

// ---------------- tc_gemm core (pre-split A, cp.async pipelined) ----------------
template <typename EPI>
__device__ __forceinline__
void tc_gemm_body(const __nv_bfloat16* __restrict__ A0h, const __nv_bfloat16* __restrict__ A0l,
                  const __nv_bfloat16* __restrict__ A1h, const __nv_bfloat16* __restrict__ A1l,
                  const __nv_bfloat16* __restrict__ Bh,  const __nv_bfloat16* __restrict__ Bl,
                  const float* __restrict__ bias, int row0, int M,
                  uint32_t sb, EPI epi) {
    int tid = threadIdx.x;
    int wid = tid >> 5, lane = tid & 31;
    int warp_m = wid & 3, warp_n = wid >> 2;
    int m0 = warp_m * 32, n0 = warp_n * 64;

    // ---- stage B via cp.async (rows: 256 bf16 contiguous = 512B) ----
#pragma unroll
    for (int it = 0; it < 16; it++) {
        int idx = tid + it * 256;          // 4096 granules per array
        int r = idx >> 5, q = idx & 31;
        uint32_t d = (uint32_t)(r * 528 + q * 16);
        CP_ASYNC16(sb + SM_BH + d, (const char*)Bh + r * 512 + q * 16);
        CP_ASYNC16(sb + SM_BL + d, (const char*)Bl + r * 512 + q * 16);
    }
    // ---- A chunk staging lambda-free helper (macro-ish) ----
    const __nv_bfloat16* srcs_h[4] = { A0h, A0h, A1h, A1h };
    const __nv_bfloat16* srcs_l[4] = { A0l, A0l, A1l, A1l };
#define STAGE_A(c)                                                                 \
    {                                                                              \
        const char* sh = (const char*)(srcs_h[c] + (size_t)row0 * F) + ((c) & 1) * 128; \
        const char* sl = (const char*)(srcs_l[c] + (size_t)row0 * F) + ((c) & 1) * 128; \
        uint32_t ab = sb + SM_A + ((c) & 1) * 2 * ABUF_SZ;                         \
        _Pragma("unroll")                                                          \
        for (int it = 0; it < 4; it++) {                                           \
            int idx = tid + it * 256;      /* 1024 granules */                     \
            int r = idx >> 3, q = idx & 7;                                         \
            uint32_t d = (uint32_t)(r * 144 + q * 16);                             \
            CP_ASYNC16(ab + d,           sh + r * 256 + q * 16);                   \
            CP_ASYNC16(ab + ABUF_SZ + d, sl + r * 256 + q * 16);                   \
        }                                                                          \
    }
    STAGE_A(0);
    CP_COMMIT();            // group0: B + A0
    STAGE_A(1);
    CP_COMMIT();            // group1: A1

    // ---- per-thread ldmatrix offsets ----
    int group = lane >> 3, within = lane & 7;
    int a_row = within + ((group == 1 || group == 3) ? 8 : 0);
    int a_col = (group >= 2) ? 8 : 0;
    int b_row = within + ((group >= 2) ? 8 : 0);
    int b_col = (group == 1 || group == 3) ? 8 : 0;
    uint32_t aoff[2];
#pragma unroll
    for (int i = 0; i < 2; i++)
        aoff[i] = (uint32_t)((m0 + i * 16 + a_row) * ASTRB + a_col) * 2;
    uint32_t boff_h[4], boff_l[4];
#pragma unroll
    for (int j = 0; j < 4; j++) {
        uint32_t off = (uint32_t)((n0 + j * 16 + b_row) * BSTR + b_col) * 2;
        boff_h[j] = sb + SM_BH + off;
        boff_l[j] = sb + SM_BL + off;
    }

    float acc[2][8][4];
#pragma unroll
    for (int i = 0; i < 2; i++)
#pragma unroll
        for (int j = 0; j < 8; j++)
#pragma unroll
            for (int q = 0; q < 4; q++) acc[i][j][q] = 0.f;

#pragma unroll
    for (int kc = 0; kc < 4; kc++) {
        if (kc < 3) { CP_WAIT1(); } else { CP_WAIT0(); }
        __syncthreads();
        uint32_t abase_h = sb + SM_A + (kc & 1) * 2 * ABUF_SZ;
        uint32_t abase_l = abase_h + ABUF_SZ;
#pragma unroll
        for (int k16 = 0; k16 < 4; k16++) {
            uint32_t ka = (uint32_t)(k16 * 16) * 2;
            uint32_t kb = (uint32_t)(kc * 64 + k16 * 16) * 2;
            uint32_t ah[2][4], al[2][4];
#pragma unroll
            for (int i = 0; i < 2; i++) {
                ldm_x4(ah[i], abase_h + aoff[i] + ka);
                ldm_x4(al[i], abase_l + aoff[i] + ka);
            }
#pragma unroll
            for (int j = 0; j < 4; j++) {
                uint32_t bh[4], bl[4];
                ldm_x4(bh, boff_h[j] + kb);
                ldm_x4(bl, boff_l[j] + kb);
#pragma unroll
                for (int i = 0; i < 2; i++) {
                    mma_bf16(acc[i][2 * j],     ah[i], bh[0], bh[1]);
                    mma_bf16(acc[i][2 * j],     ah[i], bl[0], bl[1]);
                    mma_bf16(acc[i][2 * j],     al[i], bh[0], bh[1]);
                    mma_bf16(acc[i][2 * j + 1], ah[i], bh[2], bh[3]);
                    mma_bf16(acc[i][2 * j + 1], ah[i], bl[2], bl[3]);
                    mma_bf16(acc[i][2 * j + 1], al[i], bh[2], bh[3]);
                }
            }
        }
        __syncthreads();
        if (kc < 2) { STAGE_A(kc + 2); CP_COMMIT(); }
    }
#undef STAGE_A

    // ---- epilogue from registers ----
    int g = lane >> 2, tg = lane & 3;
#pragma unroll
    for (int i = 0; i < 2; i++) {
#pragma unroll
        for (int j = 0; j < 8; j++) {
            int col = n0 + j * 8 + tg * 2;
            float b0 = bias[col], b1 = bias[col + 1];
#pragma unroll
            for (int h = 0; h < 2; h++) {
                int r = row0 + m0 + i * 16 + g + h * 8;
                if (r >= M) continue;
                size_t o = (size_t)r * F + col;
                epi(o, acc[i][j][2 * h] + b0, acc[i][j][2 * h + 1] + b1);
            }
        }
    }
}

// merged Z / HR launch: blockIdx.y selects channel
__global__ __launch_bounds__(256, 1)
void tc_gemm_zr(const float* __restrict__ H, int M) {
    extern __shared__ __align__(16) char smem[];
    uint32_t sb = smem_u32(smem);
    int y = blockIdx.y;
    int row0 = blockIdx.x * 128;
    const __nv_bfloat16* bh = g_Bh + (size_t)y * F * 256;
    const __nv_bfloat16* bl = g_Bl + (size_t)y * F * 256;
    const float* bias = g_cb + y * F;
    if (y == 0) {
        EpiZ epi{g_Z};
        tc_gemm_body(g_Xh, g_Xl, g_Hh, g_Hl, bh, bl, bias, row0, M, sb, epi);
    } else {
        EpiHR epi{g_HRh, g_HRl, H};
        tc_gemm_body(g_Xh, g_Xl, g_Hh, g_Hl, bh, bl, bias, row0, M, sb, epi);
    }
}

__global__ __launch_bounds__(256, 1)
void tc_gemm_final(const float* __restrict__ H, float* __restrict__ out, int M) {
    extern __shared__ __align__(16) char smem[];
    uint32_t sb = smem_u32(smem);
    int row0 = blockIdx.x * 128;
    EpiFinal epi{out, g_Z, H};
    tc_gemm_body(g_Xh, g_Xl, g_HRh, g_HRl,
                 g_Bh + 2 * (size_t)F * 256, g_Bl + 2 * (size_t)F * 256,
                 g_cb + 2 * F, row0, M, sb, epi);
}

// ---------------- launch ----------------
extern "C" void kernel_launch(void* const* d_in, const int* in_sizes, int n_in,
                              void* d_out, int out_size) {
    const float* X    = (const float*)d_in[0];
    const int*   eiw  = (const int*)d_in[1];
    const float* ew   = (const float*)d_in[2];
    const float* H    = (const float*)d_in[3];
    const float* W_z  = (const float*)d_in[4];
    const float* b_z  = (const float*)d_in[5];
    const float* W_r  = (const float*)d_in[6];
    const float* b_r  = (const float*)d_in[7];
    const float* W_h  = (const float*)d_in[8];
    const float* b_h  = (const float*)d_in[9];
    const float* Wl_z = (const float*)d_in[10];
    const float* bl_z = (const float*)d_in[11];
    const float* Wl_r = (const float*)d_in[12];
    const float* bl_r = (const float*)d_in[13];
    const float* Wl_h = (const float*)d_in[14];
    const float* bl_h = (const float*)d_in[15];
    float*       out  = (float*)d_out;

    int n = in_sizes[0] / F;   // 50000
    int E = in_sizes[2];       // 800000
    int n4 = n * (F / 4);

    float* xagg;
    __nv_bfloat16 *Xh, *Xl, *Hh, *Hl;
    cudaGetSymbolAddress((void**)&xagg, g_xagg);
    cudaGetSymbolAddress((void**)&Xh,   g_Xh);
    cudaGetSymbolAddress((void**)&Xl,   g_Xl);
    cudaGetSymbolAddress((void**)&Hh,   g_Hh);
    cudaGetSymbolAddress((void**)&Hl,   g_Hl);

    cudaFuncSetAttribute(tc_gemm_zr,    cudaFuncAttributeMaxDynamicSharedMemorySize, TC_SMEM);
    cudaFuncSetAttribute(tc_gemm_final, cudaFuncAttributeMaxDynamicSharedMemorySize, TC_SMEM);

    // weight / H prep (graph-independent)
    bprep_kernel<<<768, 128>>>(W_z, W_r, W_h, Wl_z, Wl_r, Wl_h);
    biasprep_kernel<<<1, 384>>>(b_z, Wl_z, bl_z, b_r, Wl_r, bl_r, b_h, Wl_h, bl_h);
    split_kernel<<<(n4 + 255) / 256, 256>>>(H, Hh, Hl, n4);

    // graph prep
    initdeg_kernel<<<(n + 255) / 256, 256>>>(n);
    probe_kernel<<<1, 256>>>(eiw);
    decode_deg_kernel<<<(E + 255) / 256, 256>>>(eiw, ew, E);
    dinv_kernel<<<(n + 255) / 256, 256>>>(n);

    // aggregate X, then split to bf16 hi/lo
    xinit_kernel<<<(n4 + 255) / 256, 256>>>(X, n);
    scatter_kernel<<<(E * 32 + 255) / 256, 256>>>(X, ew, E);
    split_kernel<<<(n4 + 255) / 256, 256>>>(xagg, Xh, Xl, n4);

    // fused linear stages
    int nb = (n + 127) / 128;
    dim3 gzr(nb, 2);
    tc_gemm_zr<<<gzr, 256, TC_SMEM>>>(H, n);
    tc_gemm_final<<<nb, 256, TC_SMEM>>>(H, out, n);
}

// round 13
// speedup vs baseline: 1.0804x; 1.0804x over previous
#include <cuda_runtime.h>
#include <cuda_bf16.h>
#include <math.h>
#include <stdint.h>

static constexpr int F    = 128;
static constexpr int NMAX = 50000;
static constexpr int EMAX = 800000;

// ---- tc_gemm smem layout (bytes) ----
static constexpr int SM_BH   = 0;         // 128 x 528B (264 bf16: 256+8 pad)
static constexpr int SM_BL   = 67584;
static constexpr int SM_A    = 135168;    // 2 bufs x (hi 18432 + lo 18432)
static constexpr int ABUF_SZ = 18432;     // 128 rows x 144B (72 bf16: 64+8 pad)
static constexpr int TC_SMEM = SM_A + 2 * 2 * ABUF_SZ;   // 208896
static constexpr int BSTR  = 264;
static constexpr int ASTRB = 72;

// ---------------- scratch ----------------
__device__ float g_xagg[NMAX * F];
__device__ float g_Z   [NMAX * F];
__device__ float g_HR  [NMAX * F];
__device__ float g_cb  [3 * F];
__device__ __nv_bfloat16 g_Bh[3 * F * 256];
__device__ __nv_bfloat16 g_Bl[3 * F * 256];
__device__ float g_deg [NMAX];
__device__ float g_dinv[NMAX];
__device__ int   g_src [EMAX];
__device__ int   g_tgt [EMAX];

// ---------------- helpers ----------------
__device__ __forceinline__ uint32_t smem_u32(const void* p) {
    uint32_t a;
    asm("{ .reg .u64 t; cvta.to.shared.u64 t, %1; cvt.u32.u64 %0, t; }" : "=r"(a) : "l"(p));
    return a;
}
__device__ __forceinline__ void ldm_x4(uint32_t* r, uint32_t addr) {
    asm volatile("ldmatrix.sync.aligned.m8n8.x4.shared.b16 {%0,%1,%2,%3}, [%4];"
                 : "=r"(r[0]), "=r"(r[1]), "=r"(r[2]), "=r"(r[3]) : "r"(addr));
}
__device__ __forceinline__ void mma_bf16(float* c, const uint32_t* a, uint32_t b0, uint32_t b1) {
    asm volatile("mma.sync.aligned.m16n8k16.row.col.f32.bf16.bf16.f32 "
                 "{%0,%1,%2,%3}, {%4,%5,%6,%7}, {%8,%9}, {%0,%1,%2,%3};"
                 : "+f"(c[0]), "+f"(c[1]), "+f"(c[2]), "+f"(c[3])
                 : "r"(a[0]), "r"(a[1]), "r"(a[2]), "r"(a[3]), "r"(b0), "r"(b1));
}
__device__ __forceinline__ uint32_t pack_bf2(float a, float b) {
    __nv_bfloat16 ha = __float2bfloat16(a), hb = __float2bfloat16(b);
    return ((uint32_t)__bfloat16_as_ushort(hb) << 16) | (uint32_t)__bfloat16_as_ushort(ha);
}

// ---------------- epilogue functors ----------------
struct EpiZ {
    float* Zp;
    __device__ __forceinline__ void operator()(size_t o, float v0, float v1) const {
        float2 r;
        r.x = 1.f / (1.f + __expf(-v0));
        r.y = 1.f / (1.f + __expf(-v1));
        *(float2*)(Zp + o) = r;
    }
};
struct EpiHR {
    float* HRp;
    const float* H;
    __device__ __forceinline__ void operator()(size_t o, float v0, float v1) const {
        float2 r;
        r.x = H[o]     * (1.f / (1.f + __expf(-v0)));
        r.y = H[o + 1] * (1.f / (1.f + __expf(-v1)));
        *(float2*)(HRp + o) = r;
    }
};
struct EpiFinal {
    float* out;
    const float* Zb;
    const float* H;
    __device__ __forceinline__ void operator()(size_t o, float v0, float v1) const {
        float z0 = Zb[o], z1 = Zb[o + 1];
        float2 r;
        r.x = z0 * H[o]     + (1.f - z0) * tanhf(v0);
        r.y = z1 * H[o + 1] + (1.f - z1) * tanhf(v1);
        *(float2*)(out + o) = r;
    }
};

// ---------------- prep kernels ----------------
__global__ void initdeg_kernel(int n) {
    int i = blockIdx.x * blockDim.x + threadIdx.x;
    if (i < n) g_deg[i] = 1.0f;   // self-loop
}

// per-block local dtype probe (64 odd words of row 0) + decode + degree accumulation
__global__ void decode_deg_kernel(const int* __restrict__ w,
                                  const float* __restrict__ ew, int E) {
    __shared__ int s_is64;
    if (threadIdx.x == 0) {
        int nz = 0;
#pragma unroll 8
        for (int i = 0; i < 64; i++) nz |= w[2 * i + 1];
        s_is64 = (nz == 0);
    }
    __syncthreads();
    int is64 = s_is64;
    int e = blockIdx.x * blockDim.x + threadIdx.x;
    if (e >= E) return;
    int s, t;
    if (is64) { s = w[2 * e]; t = w[2 * (E + e)]; }
    else      { s = w[e];     t = w[E + e];       }
    g_src[e] = s;
    g_tgt[e] = t;
    atomicAdd(&g_deg[t], ew[e]);
}

// dinv + self-loop term fused: xagg = X * dinv^2, g_dinv persisted for scatter
__global__ void xinit_kernel(const float* __restrict__ X, int n) {
    int i4 = blockIdx.x * blockDim.x + threadIdx.x;
    if (i4 >= n * (F / 4)) return;
    int node = i4 >> 5;
    float d = rsqrtf(g_deg[node]);
    if ((i4 & 31) == 0) g_dinv[node] = d;
    float d2 = d * d;
    float4 v = ((const float4*)X)[i4];
    ((float4*)g_xagg)[i4] = make_float4(v.x * d2, v.y * d2, v.z * d2, v.w * d2);
}

// one warp per edge; one v4 gather + one v4 RED per lane
__global__ void scatter_kernel(const float* __restrict__ X,
                               const float* __restrict__ ew, int E) {
    int gw   = (blockIdx.x * blockDim.x + threadIdx.x) >> 5;
    int lane = threadIdx.x & 31;
    if (gw >= E) return;
    int s = g_src[gw];
    int t = g_tgt[gw];
    float c = g_dinv[s] * ew[gw] * g_dinv[t];
    const float4* xp = (const float4*)(X + (size_t)s * F);
    float*        ap = g_xagg + (size_t)t * F + lane * 4;
    float4 v = __ldg(xp + lane);
    asm volatile("red.global.add.v4.f32 [%0], {%1, %2, %3, %4};"
                 :: "l"(ap), "f"(v.x * c), "f"(v.y * c), "f"(v.z * c), "f"(v.w * c)
                 : "memory");
}

// merged weight prep: blocks 0..767 -> B images; blocks 768..770 -> combined biases
__global__ void wprep_kernel(const float* __restrict__ Wz, const float* __restrict__ Wr, const float* __restrict__ Wh,
                             const float* __restrict__ Wlz, const float* __restrict__ Wlr, const float* __restrict__ Wlh,
                             const float* __restrict__ bz, const float* __restrict__ br, const float* __restrict__ bh,
                             const float* __restrict__ blz, const float* __restrict__ blr, const float* __restrict__ blh) {
    int bid = blockIdx.x;
    if (bid >= 768) {   // bias blocks
        int ch = bid - 768;
        int j = threadIdx.x;
        const float* b  = (ch == 0) ? bz  : (ch == 1) ? br  : bh;
        const float* Wl = (ch == 0) ? Wlz : (ch == 1) ? Wlr : Wlh;
        const float* bl = (ch == 0) ? blz : (ch == 1) ? blr : blh;
        float acc = bl[j];
        for (int k = 0; k < F; k++) acc += b[k] * Wl[k * F + j];
        g_cb[ch * F + j] = acc;
        return;
    }
    __shared__ float wrow[128];
    int ch = bid >> 8, k = bid & 255;
    int n = threadIdx.x;
    const float* Wl = (ch == 0) ? Wlz : (ch == 1) ? Wlr : Wlh;
    float v;
    if (k < 128) {
        const float* W = (ch == 0) ? Wz : (ch == 1) ? Wr : Wh;
        wrow[n] = W[k * F + n];
        __syncthreads();
        float acc = 0.f;
#pragma unroll 8
        for (int j = 0; j < F; j++) acc += wrow[j] * Wl[j * F + n];
        v = acc;
    } else {
        v = Wl[k * F + n];
    }
    __nv_bfloat16 h = __float2bfloat16(v);
    __nv_bfloat16 l = __float2bfloat16(v - __bfloat162float(h));
    size_t o = (size_t)ch * F * 256 + (size_t)n * 256 + k;
    g_Bh[o] = h;
    g_Bl[o] = l;
}

// ---------------- tc_gemm core (in-kernel split, double-buffered, 1 bar/kc) ----------------
template <typename EPI>
__device__ __forceinline__
void tc_gemm_body(const float* __restrict__ A0, const float* __restrict__ A1,
                  const __nv_bfloat16* __restrict__ Bh, const __nv_bfloat16* __restrict__ Bl,
                  const float* __restrict__ bias, int row0, int M,
                  char* smem, uint32_t sb, EPI epi) {
    int tid = threadIdx.x;
    int wid = tid >> 5, lane = tid & 31;
    int warp_m = wid & 3, warp_n = wid >> 2;
    int m0 = warp_m * 32, n0 = warp_n * 64;
    int remRows = M - row0;

    // stage B (hi+lo) into padded smem [128][BSTR]
    {
        const uint4* s0 = (const uint4*)Bh;
        const uint4* s1 = (const uint4*)Bl;
#pragma unroll
        for (int it = 0; it < 16; it++) {
            int idx = tid + it * 256;
            int r = idx >> 5, q = idx & 31;
            *(uint4*)(smem + SM_BH + r * (BSTR * 2) + q * 16) = s0[idx];
            *(uint4*)(smem + SM_BL + r * (BSTR * 2) + q * 16) = s1[idx];
        }
    }

    // per-thread conversion indices (8 float4 per thread per chunk)
    int cr[8], cq[8];
#pragma unroll
    for (int it = 0; it < 8; it++) {
        int idx = tid + it * 256;
        cr[it] = idx >> 4;
        cq[it] = idx & 15;
    }

#define LOAD_CHUNK(vv, c)                                                            \
    {                                                                                \
        const float* Asrc = (((c) < 2) ? A0 : A1) + (size_t)row0 * F + ((c) & 1) * 64; \
        _Pragma("unroll")                                                            \
        for (int it = 0; it < 8; it++) {                                             \
            vv[it] = make_float4(0.f, 0.f, 0.f, 0.f);                                \
            if (cr[it] < remRows)                                                    \
                vv[it] = *(const float4*)(Asrc + (size_t)cr[it] * F + cq[it] * 4);   \
        }                                                                            \
    }
#define CONV_CHUNK(vv, buf)                                                          \
    {                                                                                \
        uint32_t ah = sb + SM_A + (buf) * 2 * ABUF_SZ;                               \
        uint32_t al = ah + ABUF_SZ;                                                  \
        _Pragma("unroll")                                                            \
        for (int it = 0; it < 8; it++) {                                             \
            float4 _cv = vv[it];                                                     \
            __nv_bfloat16 h0 = __float2bfloat16(_cv.x), h1 = __float2bfloat16(_cv.y);\
            __nv_bfloat16 h2 = __float2bfloat16(_cv.z), h3 = __float2bfloat16(_cv.w);\
            uint32_t hi01 = ((uint32_t)__bfloat16_as_ushort(h1) << 16) | __bfloat16_as_ushort(h0); \
            uint32_t hi23 = ((uint32_t)__bfloat16_as_ushort(h3) << 16) | __bfloat16_as_ushort(h2); \
            uint32_t lo01 = pack_bf2(_cv.x - __bfloat162float(h0), _cv.y - __bfloat162float(h1));  \
            uint32_t lo23 = pack_bf2(_cv.z - __bfloat162float(h2), _cv.w - __bfloat162float(h3));  \
            uint32_t off = (uint32_t)(cr[it] * ASTRB + cq[it] * 4) * 2;              \
            *(uint2*)(smem + (ah - sb) + off) = make_uint2(hi01, hi23);              \
            *(uint2*)(smem + (al - sb) + off) = make_uint2(lo01, lo23);              \
        }                                                                            \
    }

    // ldmatrix offsets
    int group = lane >> 3, within = lane & 7;
    int a_row = within + ((group == 1 || group == 3) ? 8 : 0);
    int a_col = (group >= 2) ? 8 : 0;
    int b_row = within + ((group >= 2) ? 8 : 0);
    int b_col = (group == 1 || group == 3) ? 8 : 0;
    uint32_t aoff[2];
#pragma unroll
    for (int i = 0; i < 2; i++)
        aoff[i] = (uint32_t)((m0 + i * 16 + a_row) * ASTRB + a_col) * 2;
    uint32_t boff_h[4], boff_l[4];
#pragma unroll
    for (int j = 0; j < 4; j++) {
        uint32_t off = (uint32_t)((n0 + j * 16 + b_row) * BSTR + b_col) * 2;
        boff_h[j] = sb + SM_BH + off;
        boff_l[j] = sb + SM_BL + off;
    }

    float acc[2][8][4];
#pragma unroll
    for (int i = 0; i < 2; i++)
#pragma unroll
        for (int j = 0; j < 8; j++)
#pragma unroll
            for (int q = 0; q < 4; q++) acc[i][j][q] = 0.f;

    float4 pf[8];
    LOAD_CHUNK(pf, 0);
    CONV_CHUNK(pf, 0);

#pragma unroll
    for (int kc = 0; kc < 4; kc++) {
        __syncthreads();                      // conv(kc) visible to all
        if (kc < 3) LOAD_CHUNK(pf, kc + 1);   // prefetch overlaps MMAs below
        uint32_t abase_h = sb + SM_A + (kc & 1) * 2 * ABUF_SZ;
        uint32_t abase_l = abase_h + ABUF_SZ;
#pragma unroll
        for (int k16 = 0; k16 < 4; k16++) {
            uint32_t ka = (uint32_t)(k16 * 16) * 2;
            uint32_t kb = (uint32_t)(kc * 64 + k16 * 16) * 2;
            uint32_t ah[2][4], al[2][4];
#pragma unroll
            for (int i = 0; i < 2; i++) {
                ldm_x4(ah[i], abase_h + aoff[i] + ka);
                ldm_x4(al[i], abase_l + aoff[i] + ka);
            }
#pragma unroll
            for (int j = 0; j < 4; j++) {
                uint32_t bh[4], bl[4];
                ldm_x4(bh, boff_h[j] + kb);
                ldm_x4(bl, boff_l[j] + kb);
#pragma unroll
                for (int i = 0; i < 2; i++) {
                    mma_bf16(acc[i][2 * j],     ah[i], bh[0], bh[1]);
                    mma_bf16(acc[i][2 * j],     ah[i], bl[0], bl[1]);
                    mma_bf16(acc[i][2 * j],     al[i], bh[0], bh[1]);
                    mma_bf16(acc[i][2 * j + 1], ah[i], bh[2], bh[3]);
                    mma_bf16(acc[i][2 * j + 1], ah[i], bl[2], bl[3]);
                    mma_bf16(acc[i][2 * j + 1], al[i], bh[2], bh[3]);
                }
            }
        }
        // write NEXT chunk into the other buffer; safe: slowest peer warp is at
        // MMA(kc) reading buf kc&1, we write buf (kc+1)&1.
        if (kc < 3) CONV_CHUNK(pf, (kc + 1) & 1);
    }
#undef LOAD_CHUNK
#undef CONV_CHUNK

    // epilogue from registers
    int g = lane >> 2, tg = lane & 3;
#pragma unroll
    for (int i = 0; i < 2; i++) {
#pragma unroll
        for (int j = 0; j < 8; j++) {
            int col = n0 + j * 8 + tg * 2;
            float b0 = bias[col], b1 = bias[col + 1];
#pragma unroll
            for (int h = 0; h < 2; h++) {
                int r = row0 + m0 + i * 16 + g + h * 8;
                if (r >= M) continue;
                size_t o = (size_t)r * F + col;
                epi(o, acc[i][j][2 * h] + b0, acc[i][j][2 * h + 1] + b1);
            }
        }
    }
}

// merged Z / HR launch: blockIdx.y selects channel (0 = Z, 1 = HR)
__global__ __launch_bounds__(256, 1)
void tc_gemm_zr(const float* __restrict__ xagg, const float* __restrict__ H,
                float* __restrict__ Zp, float* __restrict__ HRp, int M) {
    extern __shared__ __align__(16) char smem[];
    uint32_t sb = smem_u32(smem);
    int y = blockIdx.y;
    int row0 = blockIdx.x * 128;
    const __nv_bfloat16* bh = g_Bh + (size_t)y * F * 256;
    const __nv_bfloat16* bl = g_Bl + (size_t)y * F * 256;
    const float* bias = g_cb + y * F;
    if (y == 0) {
        EpiZ epi{Zp};
        tc_gemm_body(xagg, H, bh, bl, bias, row0, M, smem, sb, epi);
    } else {
        EpiHR epi{HRp, H};
        tc_gemm_body(xagg, H, bh, bl, bias, row0, M, smem, sb, epi);
    }
}

__global__ __launch_bounds__(256, 1)
void tc_gemm_final(const float* __restrict__ xagg, const float* __restrict__ HR,
                   const float* __restrict__ Zb, const float* __restrict__ H,
                   float* __restrict__ out, int M) {
    extern __shared__ __align__(16) char smem[];
    uint32_t sb = smem_u32(smem);
    int row0 = blockIdx.x * 128;
    EpiFinal epi{out, Zb, H};
    tc_gemm_body(xagg, HR, g_Bh + 2 * (size_t)F * 256, g_Bl + 2 * (size_t)F * 256,
                 g_cb + 2 * F, row0, M, smem, sb, epi);
}

// ---------------- launch ----------------
extern "C" void kernel_launch(void* const* d_in, const int* in_sizes, int n_in,
                              void* d_out, int out_size) {
    const float* X    = (const float*)d_in[0];
    const int*   eiw  = (const int*)d_in[1];
    const float* ew   = (const float*)d_in[2];
    const float* H    = (const float*)d_in[3];
    const float* W_z  = (const float*)d_in[4];
    const float* b_z  = (const float*)d_in[5];
    const float* W_r  = (const float*)d_in[6];
    const float* b_r  = (const float*)d_in[7];
    const float* W_h  = (const float*)d_in[8];
    const float* b_h  = (const float*)d_in[9];
    const float* Wl_z = (const float*)d_in[10];
    const float* bl_z = (const float*)d_in[11];
    const float* Wl_r = (const float*)d_in[12];
    const float* bl_r = (const float*)d_in[13];
    const float* Wl_h = (const float*)d_in[14];
    const float* bl_h = (const float*)d_in[15];
    float*       out  = (float*)d_out;

    int n = in_sizes[0] / F;   // 50000
    int E = in_sizes[2];       // 800000
    int n4 = n * (F / 4);

    float *xagg, *Zp, *HRp;
    cudaGetSymbolAddress((void**)&xagg, g_xagg);
    cudaGetSymbolAddress((void**)&Zp,   g_Z);
    cudaGetSymbolAddress((void**)&HRp,  g_HR);

    cudaFuncSetAttribute(tc_gemm_zr,    cudaFuncAttributeMaxDynamicSharedMemorySize, TC_SMEM);
    cudaFuncSetAttribute(tc_gemm_final, cudaFuncAttributeMaxDynamicSharedMemorySize, TC_SMEM);

    initdeg_kernel<<<(n + 255) / 256, 256>>>(n);
    decode_deg_kernel<<<(E + 255) / 256, 256>>>(eiw, ew, E);
    wprep_kernel<<<771, 128>>>(W_z, W_r, W_h, Wl_z, Wl_r, Wl_h,
                               b_z, b_r, b_h, bl_z, bl_r, bl_h);
    xinit_kernel<<<(n4 + 255) / 256, 256>>>(X, n);
    scatter_kernel<<<(E * 32 + 255) / 256, 256>>>(X, ew, E);

    int nb = (n + 127) / 128;
    dim3 gzr(nb, 2);
    tc_gemm_zr<<<gzr, 256, TC_SMEM>>>(xagg, H, Zp, HRp, n);
    tc_gemm_final<<<nb, 256, TC_SMEM>>>(xagg, HRp, Zp, H, out, n);
}

// round 14
// speedup vs baseline: 1.1857x; 1.0974x over previous
#include <cuda_runtime.h>
#include <cuda_bf16.h>
#include <math.h>
#include <stdint.h>

static constexpr int F    = 128;
static constexpr int NMAX = 50000;
static constexpr int EMAX = 800000;
static constexpr int SCAN_BLOCKS = (NMAX + 255) / 256;   // 196

// ---- tc_gemm smem layout (bytes) ----
static constexpr int SM_BH   = 0;
static constexpr int SM_BL   = 67584;
static constexpr int SM_A    = 135168;
static constexpr int ABUF_SZ = 18432;
static constexpr int TC_SMEM = SM_A + 2 * 2 * ABUF_SZ;   // 208896
static constexpr int BSTR  = 264;
static constexpr int ASTRB = 72;

// ---------------- scratch ----------------
__device__ float g_xagg[NMAX * F];
__device__ float g_Z   [NMAX * F];
__device__ float g_HR  [NMAX * F];
__device__ float g_cb  [3 * F];
__device__ __nv_bfloat16 g_Bh[3 * F * 256];
__device__ __nv_bfloat16 g_Bl[3 * F * 256];
__device__ float g_deg [NMAX];
__device__ float g_dinv[NMAX];
__device__ int   g_src [EMAX];
__device__ int   g_tgt [EMAX];
// CSR build
__device__ int   g_cnt   [NMAX];
__device__ int   g_scan  [NMAX];
__device__ int   g_part  [256];
__device__ int   g_partoff[256];
__device__ int   g_beg   [NMAX];
__device__ int   g_end   [NMAX];
__device__ int   g_cursor[NMAX];
__device__ int   g_esrc  [EMAX];
__device__ float g_ecoef [EMAX];

// ---------------- helpers ----------------
__device__ __forceinline__ uint32_t smem_u32(const void* p) {
    uint32_t a;
    asm("{ .reg .u64 t; cvta.to.shared.u64 t, %1; cvt.u32.u64 %0, t; }" : "=r"(a) : "l"(p));
    return a;
}
__device__ __forceinline__ void ldm_x4(uint32_t* r, uint32_t addr) {
    asm volatile("ldmatrix.sync.aligned.m8n8.x4.shared.b16 {%0,%1,%2,%3}, [%4];"
                 : "=r"(r[0]), "=r"(r[1]), "=r"(r[2]), "=r"(r[3]) : "r"(addr));
}
__device__ __forceinline__ void mma_bf16(float* c, const uint32_t* a, uint32_t b0, uint32_t b1) {
    asm volatile("mma.sync.aligned.m16n8k16.row.col.f32.bf16.bf16.f32 "
                 "{%0,%1,%2,%3}, {%4,%5,%6,%7}, {%8,%9}, {%0,%1,%2,%3};"
                 : "+f"(c[0]), "+f"(c[1]), "+f"(c[2]), "+f"(c[3])
                 : "r"(a[0]), "r"(a[1]), "r"(a[2]), "r"(a[3]), "r"(b0), "r"(b1));
}
__device__ __forceinline__ uint32_t pack_bf2(float a, float b) {
    __nv_bfloat16 ha = __float2bfloat16(a), hb = __float2bfloat16(b);
    return ((uint32_t)__bfloat16_as_ushort(hb) << 16) | (uint32_t)__bfloat16_as_ushort(ha);
}

// ---------------- epilogue functors ----------------
struct EpiZ {
    float* Zp;
    __device__ __forceinline__ void operator()(size_t o, float v0, float v1) const {
        float2 r;
        r.x = 1.f / (1.f + __expf(-v0));
        r.y = 1.f / (1.f + __expf(-v1));
        *(float2*)(Zp + o) = r;
    }
};
struct EpiHR {
    float* HRp;
    const float* H;
    __device__ __forceinline__ void operator()(size_t o, float v0, float v1) const {
        float2 r;
        r.x = H[o]     * (1.f / (1.f + __expf(-v0)));
        r.y = H[o + 1] * (1.f / (1.f + __expf(-v1)));
        *(float2*)(HRp + o) = r;
    }
};
struct EpiFinal {
    float* out;
    const float* Zb;
    const float* H;
    __device__ __forceinline__ void operator()(size_t o, float v0, float v1) const {
        float z0 = Zb[o], z1 = Zb[o + 1];
        float2 r;
        r.x = z0 * H[o]     + (1.f - z0) * tanhf(v0);
        r.y = z1 * H[o + 1] + (1.f - z1) * tanhf(v1);
        *(float2*)(out + o) = r;
    }
};

// ---------------- graph prep ----------------
__global__ void init_kernel(int n) {
    int i = blockIdx.x * blockDim.x + threadIdx.x;
    if (i < n) { g_deg[i] = 1.0f; g_cnt[i] = 0; }
}

// dtype probe (per-block, deterministic) + decode + degree + target histogram
__global__ void decode_deg_kernel(const int* __restrict__ w,
                                  const float* __restrict__ ew, int E) {
    __shared__ int s_is64;
    if (threadIdx.x == 0) {
        int nz = 0;
#pragma unroll 8
        for (int i = 0; i < 64; i++) nz |= w[2 * i + 1];
        s_is64 = (nz == 0);
    }
    __syncthreads();
    int is64 = s_is64;
    int e = blockIdx.x * blockDim.x + threadIdx.x;
    if (e >= E) return;
    int s, t;
    if (is64) { s = w[2 * e]; t = w[2 * (E + e)]; }
    else      { s = w[e];     t = w[E + e];       }
    g_src[e] = s;
    g_tgt[e] = t;
    atomicAdd(&g_deg[t], ew[e]);
    atomicAdd(&g_cnt[t], 1);
}

// two-level scan: per-block inclusive scan + block sums
__global__ void scan1_kernel(int n) {
    __shared__ int sd[256];
    int tid = threadIdx.x;
    int i = blockIdx.x * 256 + tid;
    int v = (i < n) ? g_cnt[i] : 0;
    sd[tid] = v;
    __syncthreads();
#pragma unroll
    for (int off = 1; off < 256; off <<= 1) {
        int t = (tid >= off) ? sd[tid - off] : 0;
        __syncthreads();
        sd[tid] += t;
        __syncthreads();
    }
    if (i < n) g_scan[i] = sd[tid];
    if (tid == 255) g_part[blockIdx.x] = sd[255];
}

// scan block sums (<=256 entries), write EXCLUSIVE offsets
__global__ void scan2_kernel(int nblk) {
    __shared__ int sd[256];
    int tid = threadIdx.x;
    int v = (tid < nblk) ? g_part[tid] : 0;
    int orig = v;
    sd[tid] = v;
    __syncthreads();
#pragma unroll
    for (int off = 1; off < 256; off <<= 1) {
        int t = (tid >= off) ? sd[tid - off] : 0;
        __syncthreads();
        sd[tid] += t;
        __syncthreads();
    }
    g_partoff[tid] = sd[tid] - orig;   // exclusive
}

// finalize CSR bounds + cursors + dinv
__global__ void scan3_kernel(int n) {
    int i = blockIdx.x * blockDim.x + threadIdx.x;
    if (i >= n) return;
    int incl = g_scan[i] + g_partoff[blockIdx.x * 256 >= 0 ? (i >> 8) : 0];
    int beg = incl - g_cnt[i];
    g_beg[i] = beg;
    g_cursor[i] = beg;
    g_end[i] = incl;
    g_dinv[i] = rsqrtf(g_deg[i]);
}

// bucket fill: place (src, coef) into target-sorted arrays
__global__ void fill_kernel(const float* __restrict__ ew, int E) {
    int e = blockIdx.x * blockDim.x + threadIdx.x;
    if (e >= E) return;
    int s = g_src[e];
    int t = g_tgt[e];
    float c = g_dinv[s] * ew[e] * g_dinv[t];
    int pos = atomicAdd(&g_cursor[t], 1);
    g_esrc[pos] = s;
    g_ecoef[pos] = c;
}

// one warp per node: register-accumulate all incoming edges + self-loop term
__global__ void gather_kernel(const float* __restrict__ X, int n) {
    int gw   = (blockIdx.x * blockDim.x + threadIdx.x) >> 5;
    int lane = threadIdx.x & 31;
    if (gw >= n) return;
    int beg = g_beg[gw], end = g_end[gw];
    float d = g_dinv[gw];
    float d2 = d * d;
    float4 acc = __ldg((const float4*)(X + (size_t)gw * F) + lane);
    acc.x *= d2; acc.y *= d2; acc.z *= d2; acc.w *= d2;
    int e = beg;
    for (; e + 1 < end; e += 2) {
        int   s0 = g_esrc[e],     s1 = g_esrc[e + 1];
        float c0 = g_ecoef[e],    c1 = g_ecoef[e + 1];
        float4 v0 = __ldg((const float4*)(X + (size_t)s0 * F) + lane);
        float4 v1 = __ldg((const float4*)(X + (size_t)s1 * F) + lane);
        acc.x += c0 * v0.x + c1 * v1.x;
        acc.y += c0 * v0.y + c1 * v1.y;
        acc.z += c0 * v0.z + c1 * v1.z;
        acc.w += c0 * v0.w + c1 * v1.w;
    }
    if (e < end) {
        int   s0 = g_esrc[e];
        float c0 = g_ecoef[e];
        float4 v0 = __ldg((const float4*)(X + (size_t)s0 * F) + lane);
        acc.x += c0 * v0.x; acc.y += c0 * v0.y;
        acc.z += c0 * v0.z; acc.w += c0 * v0.w;
    }
    ((float4*)(g_xagg + (size_t)gw * F))[lane] = acc;
}

// merged weight prep: blocks 0..767 -> B images; blocks 768..770 -> combined biases
__global__ void wprep_kernel(const float* __restrict__ Wz, const float* __restrict__ Wr, const float* __restrict__ Wh,
                             const float* __restrict__ Wlz, const float* __restrict__ Wlr, const float* __restrict__ Wlh,
                             const float* __restrict__ bz, const float* __restrict__ br, const float* __restrict__ bh,
                             const float* __restrict__ blz, const float* __restrict__ blr, const float* __restrict__ blh) {
    int bid = blockIdx.x;
    if (bid >= 768) {
        int ch = bid - 768;
        int j = threadIdx.x;
        const float* b  = (ch == 0) ? bz  : (ch == 1) ? br  : bh;
        const float* Wl = (ch == 0) ? Wlz : (ch == 1) ? Wlr : Wlh;
        const float* bl = (ch == 0) ? blz : (ch == 1) ? blr : blh;
        float acc = bl[j];
        for (int k = 0; k < F; k++) acc += b[k] * Wl[k * F + j];
        g_cb[ch * F + j] = acc;
        return;
    }
    __shared__ float wrow[128];
    int ch = bid >> 8, k = bid & 255;
    int n = threadIdx.x;
    const float* Wl = (ch == 0) ? Wlz : (ch == 1) ? Wlr : Wlh;
    float v;
    if (k < 128) {
        const float* W = (ch == 0) ? Wz : (ch == 1) ? Wr : Wh;
        wrow[n] = W[k * F + n];
        __syncthreads();
        float acc = 0.f;
#pragma unroll 8
        for (int j = 0; j < F; j++) acc += wrow[j] * Wl[j * F + n];
        v = acc;
    } else {
        v = Wl[k * F + n];
    }
    __nv_bfloat16 h = __float2bfloat16(v);
    __nv_bfloat16 l = __float2bfloat16(v - __bfloat162float(h));
    size_t o = (size_t)ch * F * 256 + (size_t)n * 256 + k;
    g_Bh[o] = h;
    g_Bl[o] = l;
}

// ---------------- tc_gemm core (unchanged from the 321.5us kernel) ----------------
template <typename EPI>
__device__ __forceinline__
void tc_gemm_body(const float* __restrict__ A0, const float* __restrict__ A1,
                  const __nv_bfloat16* __restrict__ Bh, const __nv_bfloat16* __restrict__ Bl,
                  const float* __restrict__ bias, int row0, int M,
                  char* smem, uint32_t sb, EPI epi) {
    int tid = threadIdx.x;
    int wid = tid >> 5, lane = tid & 31;
    int warp_m = wid & 3, warp_n = wid >> 2;
    int m0 = warp_m * 32, n0 = warp_n * 64;
    int remRows = M - row0;

    {
        const uint4* s0 = (const uint4*)Bh;
        const uint4* s1 = (const uint4*)Bl;
#pragma unroll
        for (int it = 0; it < 16; it++) {
            int idx = tid + it * 256;
            int r = idx >> 5, q = idx & 31;
            *(uint4*)(smem + SM_BH + r * (BSTR * 2) + q * 16) = s0[idx];
            *(uint4*)(smem + SM_BL + r * (BSTR * 2) + q * 16) = s1[idx];
        }
    }

    int cr[8], cq[8];
#pragma unroll
    for (int it = 0; it < 8; it++) {
        int idx = tid + it * 256;
        cr[it] = idx >> 4;
        cq[it] = idx & 15;
    }

#define LOAD_CHUNK(vv, c)                                                            \
    {                                                                                \
        const float* Asrc = (((c) < 2) ? A0 : A1) + (size_t)row0 * F + ((c) & 1) * 64; \
        _Pragma("unroll")                                                            \
        for (int it = 0; it < 8; it++) {                                             \
            vv[it] = make_float4(0.f, 0.f, 0.f, 0.f);                                \
            if (cr[it] < remRows)                                                    \
                vv[it] = *(const float4*)(Asrc + (size_t)cr[it] * F + cq[it] * 4);   \
        }                                                                            \
    }
#define CONV_CHUNK(vv, buf)                                                          \
    {                                                                                \
        uint32_t ah = sb + SM_A + (buf) * 2 * ABUF_SZ;                               \
        uint32_t al = ah + ABUF_SZ;                                                  \
        _Pragma("unroll")                                                            \
        for (int it = 0; it < 8; it++) {                                             \
            float4 _cv = vv[it];                                                     \
            __nv_bfloat16 h0 = __float2bfloat16(_cv.x), h1 = __float2bfloat16(_cv.y);\
            __nv_bfloat16 h2 = __float2bfloat16(_cv.z), h3 = __float2bfloat16(_cv.w);\
            uint32_t hi01 = ((uint32_t)__bfloat16_as_ushort(h1) << 16) | __bfloat16_as_ushort(h0); \
            uint32_t hi23 = ((uint32_t)__bfloat16_as_ushort(h3) << 16) | __bfloat16_as_ushort(h2); \
            uint32_t lo01 = pack_bf2(_cv.x - __bfloat162float(h0), _cv.y - __bfloat162float(h1));  \
            uint32_t lo23 = pack_bf2(_cv.z - __bfloat162float(h2), _cv.w - __bfloat162float(h3));  \
            uint32_t off = (uint32_t)(cr[it] * ASTRB + cq[it] * 4) * 2;              \
            *(uint2*)(smem + (ah - sb) + off) = make_uint2(hi01, hi23);              \
            *(uint2*)(smem + (al - sb) + off) = make_uint2(lo01, lo23);              \
        }                                                                            \
    }

    int group = lane >> 3, within = lane & 7;
    int a_row = within + ((group == 1 || group == 3) ? 8 : 0);
    int a_col = (group >= 2) ? 8 : 0;
    int b_row = within + ((group >= 2) ? 8 : 0);
    int b_col = (group == 1 || group == 3) ? 8 : 0;
    uint32_t aoff[2];
#pragma unroll
    for (int i = 0; i < 2; i++)
        aoff[i] = (uint32_t)((m0 + i * 16 + a_row) * ASTRB + a_col) * 2;
    uint32_t boff_h[4], boff_l[4];
#pragma unroll
    for (int j = 0; j < 4; j++) {
        uint32_t off = (uint32_t)((n0 + j * 16 + b_row) * BSTR + b_col) * 2;
        boff_h[j] = sb + SM_BH + off;
        boff_l[j] = sb + SM_BL + off;
    }

    float acc[2][8][4];
#pragma unroll
    for (int i = 0; i < 2; i++)
#pragma unroll
        for (int j = 0; j < 8; j++)
#pragma unroll
            for (int q = 0; q < 4; q++) acc[i][j][q] = 0.f;

    float4 pf[8];
    LOAD_CHUNK(pf, 0);
    CONV_CHUNK(pf, 0);

#pragma unroll
    for (int kc = 0; kc < 4; kc++) {
        __syncthreads();
        if (kc < 3) LOAD_CHUNK(pf, kc + 1);
        uint32_t abase_h = sb + SM_A + (kc & 1) * 2 * ABUF_SZ;
        uint32_t abase_l = abase_h + ABUF_SZ;
#pragma unroll
        for (int k16 = 0; k16 < 4; k16++) {
            uint32_t ka = (uint32_t)(k16 * 16) * 2;
            uint32_t kb = (uint32_t)(kc * 64 + k16 * 16) * 2;
            uint32_t ah[2][4], al[2][4];
#pragma unroll
            for (int i = 0; i < 2; i++) {
                ldm_x4(ah[i], abase_h + aoff[i] + ka);
                ldm_x4(al[i], abase_l + aoff[i] + ka);
            }
#pragma unroll
            for (int j = 0; j < 4; j++) {
                uint32_t bh[4], bl[4];
                ldm_x4(bh, boff_h[j] + kb);
                ldm_x4(bl, boff_l[j] + kb);
#pragma unroll
                for (int i = 0; i < 2; i++) {
                    mma_bf16(acc[i][2 * j],     ah[i], bh[0], bh[1]);
                    mma_bf16(acc[i][2 * j],     ah[i], bl[0], bl[1]);
                    mma_bf16(acc[i][2 * j],     al[i], bh[0], bh[1]);
                    mma_bf16(acc[i][2 * j + 1], ah[i], bh[2], bh[3]);
                    mma_bf16(acc[i][2 * j + 1], ah[i], bl[2], bl[3]);
                    mma_bf16(acc[i][2 * j + 1], al[i], bh[2], bh[3]);
                }
            }
        }
        if (kc < 3) CONV_CHUNK(pf, (kc + 1) & 1);
    }
#undef LOAD_CHUNK
#undef CONV_CHUNK

    int g = lane >> 2, tg = lane & 3;
#pragma unroll
    for (int i = 0; i < 2; i++) {
#pragma unroll
        for (int j = 0; j < 8; j++) {
            int col = n0 + j * 8 + tg * 2;
            float b0 = bias[col], b1 = bias[col + 1];
#pragma unroll
            for (int h = 0; h < 2; h++) {
                int r = row0 + m0 + i * 16 + g + h * 8;
                if (r >= M) continue;
                size_t o = (size_t)r * F + col;
                epi(o, acc[i][j][2 * h] + b0, acc[i][j][2 * h + 1] + b1);
            }
        }
    }
}

__global__ __launch_bounds__(256, 1)
void tc_gemm_zr(const float* __restrict__ xagg, const float* __restrict__ H,
                float* __restrict__ Zp, float* __restrict__ HRp, int M) {
    extern __shared__ __align__(16) char smem[];
    uint32_t sb = smem_u32(smem);
    int y = blockIdx.y;
    int row0 = blockIdx.x * 128;
    const __nv_bfloat16* bh = g_Bh + (size_t)y * F * 256;
    const __nv_bfloat16* bl = g_Bl + (size_t)y * F * 256;
    const float* bias = g_cb + y * F;
    if (y == 0) {
        EpiZ epi{Zp};
        tc_gemm_body(xagg, H, bh, bl, bias, row0, M, smem, sb, epi);
    } else {
        EpiHR epi{HRp, H};
        tc_gemm_body(xagg, H, bh, bl, bias, row0, M, smem, sb, epi);
    }
}

__global__ __launch_bounds__(256, 1)
void tc_gemm_final(const float* __restrict__ xagg, const float* __restrict__ HR,
                   const float* __restrict__ Zb, const float* __restrict__ H,
                   float* __restrict__ out, int M) {
    extern __shared__ __align__(16) char smem[];
    uint32_t sb = smem_u32(smem);
    int row0 = blockIdx.x * 128;
    EpiFinal epi{out, Zb, H};
    tc_gemm_body(xagg, HR, g_Bh + 2 * (size_t)F * 256, g_Bl + 2 * (size_t)F * 256,
                 g_cb + 2 * F, row0, M, smem, sb, epi);
}

// ---------------- launch ----------------
extern "C" void kernel_launch(void* const* d_in, const int* in_sizes, int n_in,
                              void* d_out, int out_size) {
    const float* X    = (const float*)d_in[0];
    const int*   eiw  = (const int*)d_in[1];
    const float* ew   = (const float*)d_in[2];
    const float* H    = (const float*)d_in[3];
    const float* W_z  = (const float*)d_in[4];
    const float* b_z  = (const float*)d_in[5];
    const float* W_r  = (const float*)d_in[6];
    const float* b_r  = (const float*)d_in[7];
    const float* W_h  = (const float*)d_in[8];
    const float* b_h  = (const float*)d_in[9];
    const float* Wl_z = (const float*)d_in[10];
    const float* bl_z = (const float*)d_in[11];
    const float* Wl_r = (const float*)d_in[12];
    const float* bl_r = (const float*)d_in[13];
    const float* Wl_h = (const float*)d_in[14];
    const float* bl_h = (const float*)d_in[15];
    float*       out  = (float*)d_out;

    int n = in_sizes[0] / F;   // 50000
    int E = in_sizes[2];       // 800000

    float *xagg, *Zp, *HRp;
    cudaGetSymbolAddress((void**)&xagg, g_xagg);
    cudaGetSymbolAddress((void**)&Zp,   g_Z);
    cudaGetSymbolAddress((void**)&HRp,  g_HR);

    cudaFuncSetAttribute(tc_gemm_zr,    cudaFuncAttributeMaxDynamicSharedMemorySize, TC_SMEM);
    cudaFuncSetAttribute(tc_gemm_final, cudaFuncAttributeMaxDynamicSharedMemorySize, TC_SMEM);

    int nblk = (n + 255) / 256;   // 196
    init_kernel<<<nblk, 256>>>(n);
    decode_deg_kernel<<<(E + 255) / 256, 256>>>(eiw, ew, E);
    wprep_kernel<<<771, 128>>>(W_z, W_r, W_h, Wl_z, Wl_r, Wl_h,
                               b_z, b_r, b_h, bl_z, bl_r, bl_h);
    scan1_kernel<<<nblk, 256>>>(n);
    scan2_kernel<<<1, 256>>>(nblk);
    scan3_kernel<<<nblk, 256>>>(n);
    fill_kernel<<<(E + 255) / 256, 256>>>(ew, E);
    gather_kernel<<<(n * 32 + 255) / 256, 256>>>(X, n);

    int nb = (n + 127) / 128;
    dim3 gzr(nb, 2);
    tc_gemm_zr<<<gzr, 256, TC_SMEM>>>(xagg, H, Zp, HRp, n);
    tc_gemm_final<<<nb, 256, TC_SMEM>>>(xagg, HRp, Zp, H, out, n);
}